// round 14
// baseline (speedup 1.0000x reference)
#include <cuda_runtime.h>
#include <cuda_bf16.h>
#include <math.h>
#include <stdint.h>

#define AN 4096
#define CN 8
#define FN 64
#define NTHREADS 256
#define DIST_BLOCKS 1024

// ---------------- device scratch (no allocation allowed) --------------------
__device__ float          g_xn[CN * AN * FN];   // [c][a][f] normalized fp32
__device__ int8_t         g_xq[CN * AN * 64];   // [c][a][f] int8 quantized
__device__ ulonglong2     g_top[CN * AN];       // top-2 packed keys per row
__device__ float          g_partial[DIST_BLOCKS];
__device__ unsigned int   g_done;

// ---------------- PTX helpers (generic sm_80+ ISA only) ---------------------
static __device__ __forceinline__ uint32_t smem_u32(const void* p) {
    uint32_t a;
    asm("{ .reg .u64 t; cvta.to.shared.u64 t, %1; cvt.u32.u64 %0, t; }"
        : "=r"(a) : "l"(p));
    return a;
}

#define CP16(dst, src) \
    asm volatile("cp.async.cg.shared.global [%0], [%1], 16;" :: "r"(dst), "l"(src))
#define CP_COMMIT() asm volatile("cp.async.commit_group;" ::: "memory")
#define CP_WAIT0()  asm volatile("cp.async.wait_group 0;" ::: "memory")

static __device__ __forceinline__ void ldsm_x4(uint32_t* d, uint32_t addr) {
    asm volatile("ldmatrix.sync.aligned.m8n8.x4.shared.b16 {%0,%1,%2,%3}, [%4];"
                 : "=r"(d[0]), "=r"(d[1]), "=r"(d[2]), "=r"(d[3]) : "r"(addr));
}

static __device__ __forceinline__ void mma_s8(int* c, const uint32_t* a,
                                              const uint32_t* b) {
    asm volatile(
        "mma.sync.aligned.m16n8k32.row.col.s32.s8.s8.s32 "
        "{%0,%1,%2,%3}, {%4,%5,%6,%7}, {%8,%9}, {%0,%1,%2,%3};"
        : "+r"(c[0]), "+r"(c[1]), "+r"(c[2]), "+r"(c[3])
        : "r"(a[0]), "r"(a[1]), "r"(a[2]), "r"(a[3]), "r"(b[0]), "r"(b[1]));
}

// swizzled byte offset of 16B chunk (r, ch) in a 128-row x 64B int8 tile.
// ch in [0,4); XOR with (r>>1)&3 makes ldmatrix 8-row phases conflict-free
// (bank base = {0,16} by row parity, + 4*chunk distributes within).
static __device__ __forceinline__ uint32_t swz64(uint32_t r, uint32_t ch) {
    return r * 64u + ((ch ^ ((r >> 1) & 3u)) << 4);
}

// order-preserving int32->u32, packed with (4095 - idx): u64-max picks
// (max value, then min index) — jnp.argmax first-index tie-break.
static __device__ __forceinline__ unsigned long long pack_key_i(int v, int idx) {
    uint32_t u = (uint32_t)v ^ 0x80000000u;
    return ((unsigned long long)u << 32) | (uint32_t)(4095 - idx);
}

// top-2 merge of two sorted (k1>=k2) pairs over disjoint candidate sets
static __device__ __forceinline__ void merge2(unsigned long long& a1,
                                              unsigned long long& a2,
                                              unsigned long long b1,
                                              unsigned long long b2) {
    if (b1 > a1) { a2 = (a1 > b2) ? a1 : b2; a1 = b1; }
    else         { a2 = (a2 > b1) ? a2 : b1; }
}

// ---------------------------------------------------------------------------
// Kernel 1: normalize rows -> fp32 (c-major) + int8 quantized; reset g_done
// ---------------------------------------------------------------------------
__global__ void k_normalize(const float* __restrict__ x) {
    int gtid = blockIdx.x * blockDim.x + threadIdx.x;
    if (gtid == 0) g_done = 0;
    int warp = gtid >> 5;
    int lane = threadIdx.x & 31;
    if (warp >= AN * CN) return;
    int a = warp / CN;
    int c = warp % CN;
    const float2* row = (const float2*)(x + ((size_t)a * CN + c) * FN);
    float2 v = row[lane];
    float ss = v.x * v.x + v.y * v.y;
    #pragma unroll
    for (int o = 16; o > 0; o >>= 1) ss += __shfl_xor_sync(0xffffffffu, ss, o);
    float inv = 1.0f / fmaxf(sqrtf(ss), 1e-6f);
    float nx = v.x * inv, ny = v.y * inv;

    float2* dst = (float2*)(g_xn + ((size_t)c * AN + a) * FN);
    dst[lane] = make_float2(nx, ny);

    char2 q;
    q.x = (char)__float2int_rn(nx * 127.0f);
    q.y = (char)__float2int_rn(ny * 127.0f);
    ((char2*)(g_xq + ((size_t)c * AN + a) * 64))[lane] = q;
}

// ---------------------------------------------------------------------------
// Kernel 2: int8 IMMA screening GEMM, full sweep, top-2 per row in regs.
// Deferred-fold epilogue (tile t-1 folded during tile t's issue stream).
// ---------------------------------------------------------------------------
#define SM_A    0
#define SM_B0   8192
#define SM_B1   16384
#define SM_RED  24576      // 128 rows x 4 warps x 16B = 8 KB
#define SMEM_BYTES 32768

extern __shared__ __align__(1024) uint8_t dsm[];

__global__ __launch_bounds__(NTHREADS, 2) void k_screen() {
    uint32_t sb = smem_u32(dsm);
    int tid = threadIdx.x;
    int lane = tid & 31;
    int wid = tid >> 5;
    int wm = wid >> 2;
    int wn = wid & 3;
    int c = blockIdx.y;
    int row0 = blockIdx.x * 128;

    const char* xc = (const char*)(g_xq + (size_t)c * AN * 64);  // 64B rows

    uint32_t a_rl = (uint32_t)((lane & 7) + ((lane >> 3) & 1) * 8);
    uint32_t a_cs = (uint32_t)(lane >> 4);
    uint32_t b_nl = (uint32_t)((lane & 7) + (lane >> 4) * 8);
    uint32_t b_cs = (uint32_t)((lane >> 3) & 1);
    uint32_t arow = (uint32_t)(wm * 64);

    int rv1[8], rv2[8];
    int ri1[8], ri2[8];
    #pragma unroll
    for (int s = 0; s < 8; s++) {
        rv1[s] = -0x50000000; rv2[s] = -0x60000000; ri1[s] = 0; ri2[s] = 0;
    }

    int acc[4][4][4];

    // fold tile pt's accumulators into the running top-2 (branchless, int).
    auto fold = [&](int pt, bool maskdiag) {
        #pragma unroll
        for (int mi = 0; mi < 4; mi++) {
            #pragma unroll
            for (int hh = 0; hh < 2; hh++) {
                int s = mi * 2 + hh;
                int lrow = wm * 64 + mi * 16 + (lane >> 2) + hh * 8;
                int bv = -0x7F000000;
                int bc = 0;
                #pragma unroll
                for (int ni = 0; ni < 4; ni++) {
                    #pragma unroll
                    for (int q = 0; q < 2; q++) {
                        int v = acc[mi][ni][hh * 2 + q];
                        if (maskdiag) {
                            int cc = wn * 32 + ni * 8 + (lane & 3) * 2 + q;
                            v = (cc == lrow) ? -0x40000000 : v;
                        }
                        int code = ni * 2 + q;       // ascending col within thread
                        bool g = v > bv;             // strict > keeps lowest col
                        bv = g ? v : bv;
                        bc = g ? code : bc;
                    }
                }
                int idx = pt * 128 + wn * 32 + (bc >> 1) * 8 + (lane & 3) * 2 + (bc & 1);
                bool g1 = bv > rv1[s];
                bool g2 = bv > rv2[s];
                ri2[s] = g1 ? ri1[s] : (g2 ? idx : ri2[s]);
                rv2[s] = g1 ? rv1[s] : (g2 ? bv : rv2[s]);
                ri1[s] = g1 ? idx : ri1[s];
                rv1[s] = g1 ? bv : rv1[s];
            }
        }
    };

    // ---- prologue: A tile + B tile 0 (one cp.async group; 512 chunks each)
    #pragma unroll
    for (int u = 0; u < 2; u++) {
        int s = tid + u * NTHREADS;          // 0..511
        uint32_t r = (uint32_t)(s >> 2), ch = (uint32_t)(s & 3);
        CP16(sb + SM_A  + swz64(r, ch), xc + (size_t)(row0 + r) * 64 + ch * 16);
        CP16(sb + SM_B0 + swz64(r, ch), xc + (size_t)r * 64 + ch * 16);
    }
    CP_COMMIT();

    for (int t = 0; t < 32; t++) {
        CP_WAIT0();          // tile t's data landed
        __syncthreads();     // publish + fence buffer reuse

        if (t + 1 < 32) {    // prefetch next B into the other buffer
            uint32_t bufn = sb + ((t & 1) ? SM_B0 : SM_B1);
            const char* bsrc = xc + (size_t)(t + 1) * 128 * 64;
            #pragma unroll
            for (int u = 0; u < 2; u++) {
                int s = tid + u * NTHREADS;
                uint32_t r = (uint32_t)(s >> 2), ch = (uint32_t)(s & 3);
                CP16(bufn + swz64(r, ch), bsrc + (size_t)r * 64 + ch * 16);
            }
            CP_COMMIT();
        }

        // deferred epilogue of tile t-1 — overlaps the IMMA issue below
        if (t > 0) {
            if (t - 1 == (int)blockIdx.x) fold(t - 1, true);
            else                          fold(t - 1, false);
        }

        // ---- IMMA tile t: K=64 int8 = 2 k-steps of k32 ----
        #pragma unroll
        for (int mi = 0; mi < 4; mi++)
            #pragma unroll
            for (int ni = 0; ni < 4; ni++)
                #pragma unroll
                for (int q = 0; q < 4; q++) acc[mi][ni][q] = 0;

        uint32_t bufc = sb + ((t & 1) ? SM_B1 : SM_B0);
        #pragma unroll
        for (int ks = 0; ks < 2; ks++) {
            uint32_t kc = (uint32_t)(ks * 2);
            uint32_t af[4][4], bf[2][4];
            #pragma unroll
            for (int mi = 0; mi < 4; mi++)
                ldsm_x4(af[mi], sb + SM_A + swz64(arow + (uint32_t)(mi * 16) + a_rl, kc + a_cs));
            #pragma unroll
            for (int g = 0; g < 2; g++)
                ldsm_x4(bf[g], bufc + swz64((uint32_t)(wn * 32 + g * 16) + b_nl, kc + b_cs));
            #pragma unroll
            for (int mi = 0; mi < 4; mi++)
                #pragma unroll
                for (int ni = 0; ni < 4; ni++)
                    mma_s8(acc[mi][ni], af[mi], &bf[ni >> 1][(ni & 1) * 2]);
        }
    }

    // fold the last tile (exposed — 1/32 of total)
    if (31 == (int)blockIdx.x) fold(31, true);
    else                       fold(31, false);

    // ---- final top-2 reduce: quad -> smem -> 4 wn warps -> g_top ----
    __syncthreads();
    ulonglong2* red = (ulonglong2*)(dsm + SM_RED);
    #pragma unroll
    for (int mi = 0; mi < 4; mi++) {
        #pragma unroll
        for (int hh = 0; hh < 2; hh++) {
            int s = mi * 2 + hh;
            unsigned long long k1 = pack_key_i(rv1[s], ri1[s]);
            unsigned long long k2 = pack_key_i(rv2[s], ri2[s]);
            #pragma unroll
            for (int o = 2; o > 0; o >>= 1) {
                unsigned long long o1 = __shfl_down_sync(0xffffffffu, k1, o, 4);
                unsigned long long o2 = __shfl_down_sync(0xffffffffu, k2, o, 4);
                merge2(k1, k2, o1, o2);
            }
            if ((lane & 3) == 0) {
                int lrow = wm * 64 + mi * 16 + (lane >> 2) + hh * 8;
                red[lrow * 4 + wn] = make_ulonglong2(k1, k2);
            }
        }
    }
    __syncthreads();
    if (tid < 128) {
        ulonglong2 a = red[tid * 4];
        #pragma unroll
        for (int w = 1; w < 4; w++) {
            ulonglong2 b = red[tid * 4 + w];
            merge2(a.x, a.y, b.x, b.y);
        }
        g_top[(size_t)c * AN + row0 + tid] = a;
    }
}

// ---------------------------------------------------------------------------
// Kernel 3: exact fp32 top-2 refinement + distance + fused final reduction
// ---------------------------------------------------------------------------
__global__ void k_dist(float* __restrict__ out) {
    int gwarp  = (blockIdx.x * blockDim.x + threadIdx.x) >> 5;
    int lane   = threadIdx.x & 31;
    int nwarps = (gridDim.x * blockDim.x) >> 5;
    float acc = 0.0f;
    for (int item = gwarp; item < CN * AN; item += nwarps) {
        ulonglong2 k = g_top[item];
        int iA = 4095 - (int)(uint32_t)(k.x & 0xFFFFFFFFull);
        int iB = 4095 - (int)(uint32_t)(k.y & 0xFFFFFFFFull);
        int c = item >> 12;
        const float2* pa = (const float2*)(g_xn + (size_t)item * FN);
        const float2* p1 = (const float2*)(g_xn + ((size_t)c * AN + iA) * FN);
        const float2* p2 = (const float2*)(g_xn + ((size_t)c * AN + iB) * FN);
        float2 va = pa[lane], v1 = p1[lane], v2 = p2[lane];
        float s1 = va.x * v1.x + va.y * v1.y;
        float s2 = va.x * v2.x + va.y * v2.y;
        #pragma unroll
        for (int o = 16; o > 0; o >>= 1) {
            s1 += __shfl_xor_sync(0xffffffffu, s1, o);
            s2 += __shfl_xor_sync(0xffffffffu, s2, o);
        }
        bool useA = (s1 > s2) || (s1 == s2 && iA < iB);
        float2 vb = useA ? v1 : v2;
        float dx = va.x - vb.x + 1e-6f;
        float dy = va.y - vb.y + 1e-6f;
        float ss = dx * dx + dy * dy;
        #pragma unroll
        for (int o = 16; o > 0; o >>= 1) ss += __shfl_xor_sync(0xffffffffu, ss, o);
        if (lane == 0) acc -= logf(sqrtf(ss) + 1e-6f);
    }
    __shared__ float wsum[8];
    __shared__ float smf[256];
    if (lane == 0) wsum[threadIdx.x >> 5] = acc;
    __syncthreads();
    if (threadIdx.x == 0) {
        float s = 0.0f;
        #pragma unroll
        for (int i = 0; i < 8; i++) s += wsum[i];
        g_partial[blockIdx.x] = s;
        __threadfence();
        unsigned t = atomicInc(&g_done, 0xFFFFFFFFu);
        wsum[0] = (t == gridDim.x - 1) ? 1.0f : 0.0f;
    }
    __syncthreads();
    if (wsum[0] != 0.0f) {              // last block: deterministic final sum
        float s = 0.0f;
        #pragma unroll
        for (int u = 0; u < DIST_BLOCKS / 256; u++)
            s += g_partial[threadIdx.x + u * 256];
        smf[threadIdx.x] = s;
        __syncthreads();
        for (int st = 128; st > 0; st >>= 1) {
            if (threadIdx.x < st) smf[threadIdx.x] += smf[threadIdx.x + st];
            __syncthreads();
        }
        if (threadIdx.x == 0) out[0] = smf[0] / (float)(CN * AN);
    }
}

// ---------------------------------------------------------------------------
extern "C" void kernel_launch(void* const* d_in, const int* in_sizes, int n_in,
                              void* d_out, int out_size) {
    const float* x = (const float*)d_in[0];
    float* out = (float*)d_out;
    (void)in_sizes; (void)n_in; (void)out_size;

    cudaFuncSetAttribute(k_screen,
                         cudaFuncAttributeMaxDynamicSharedMemorySize, SMEM_BYTES);

    k_normalize<<<(AN * CN) / 8, NTHREADS>>>(x);
    k_screen<<<dim3(32, CN), NTHREADS, SMEM_BYTES>>>();
    k_dist<<<DIST_BLOCKS, NTHREADS>>>(out);
}

// round 15
// speedup vs baseline: 1.8556x; 1.8556x over previous
#include <cuda_runtime.h>
#include <cuda_bf16.h>
#include <math.h>
#include <stdint.h>

#define AN 4096
#define CN 8
#define FN 64
#define NTHREADS 256
#define DIST_BLOCKS 1024

// ---------------- device scratch (no allocation allowed) --------------------
__device__ float          g_xn[CN * AN * FN];   // [c][a][f] normalized fp32
__device__ __nv_bfloat16  g_xp[CN * AN * 64];   // [c][a][f] bf16 (screen)
__device__ ulonglong2     g_q4[CN * AN * 4];    // [c][rb][row][q] partial top2
__device__ float          g_partial[DIST_BLOCKS];
__device__ unsigned int   g_done;

// ---------------- PTX helpers (generic sm_80+ ISA only) ---------------------
static __device__ __forceinline__ uint32_t smem_u32(const void* p) {
    uint32_t a;
    asm("{ .reg .u64 t; cvta.to.shared.u64 t, %1; cvt.u32.u64 %0, t; }"
        : "=r"(a) : "l"(p));
    return a;
}

#define CP16(dst, src) \
    asm volatile("cp.async.cg.shared.global [%0], [%1], 16;" :: "r"(dst), "l"(src))
#define CP_COMMIT() asm volatile("cp.async.commit_group;" ::: "memory")
#define CP_WAIT0()  asm volatile("cp.async.wait_group 0;" ::: "memory")

static __device__ __forceinline__ void ldsm_x4(uint32_t* d, uint32_t addr) {
    asm volatile("ldmatrix.sync.aligned.m8n8.x4.shared.b16 {%0,%1,%2,%3}, [%4];"
                 : "=r"(d[0]), "=r"(d[1]), "=r"(d[2]), "=r"(d[3]) : "r"(addr));
}

static __device__ __forceinline__ void mma_bf16(float* c, const uint32_t* a,
                                                const uint32_t* b) {
    asm volatile(
        "mma.sync.aligned.m16n8k16.row.col.f32.bf16.bf16.f32 "
        "{%0,%1,%2,%3}, {%4,%5,%6,%7}, {%8,%9}, {%0,%1,%2,%3};"
        : "+f"(c[0]), "+f"(c[1]), "+f"(c[2]), "+f"(c[3])
        : "r"(a[0]), "r"(a[1]), "r"(a[2]), "r"(a[3]), "r"(b[0]), "r"(b[1]));
}

// swizzled byte offset of 16B chunk (r, ch) in a 128-row x 128B bf16 tile
static __device__ __forceinline__ uint32_t swz128(uint32_t r, uint32_t ch) {
    return r * 128u + ((ch ^ (r & 7u)) << 4);
}

// order-preserving float->u32, packed with (4095 - idx): u64-max picks
// (max value, then min index) — jnp.argmax first-index tie-break.
static __device__ __forceinline__ unsigned long long pack_key(float v, int idx) {
    uint32_t u = __float_as_uint(v);
    u = (u & 0x80000000u) ? ~u : (u | 0x80000000u);
    return ((unsigned long long)u << 32) | (uint32_t)(4095 - idx);
}

// top-2 merge of two sorted (k1>=k2) pairs over disjoint candidate sets
static __device__ __forceinline__ void merge2(unsigned long long& a1,
                                              unsigned long long& a2,
                                              unsigned long long b1,
                                              unsigned long long b2) {
    if (b1 > a1) { a2 = (a1 > b2) ? a1 : b2; a1 = b1; }
    else         { a2 = (a2 > b1) ? a2 : b1; }
}

// ---------------------------------------------------------------------------
// Kernel 1: normalize rows -> fp32 (c-major) + bf16 row; reset g_done
// ---------------------------------------------------------------------------
__global__ void k_normalize(const float* __restrict__ x) {
    int gtid = blockIdx.x * blockDim.x + threadIdx.x;
    if (gtid == 0) g_done = 0;
    int warp = gtid >> 5;
    int lane = threadIdx.x & 31;
    if (warp >= AN * CN) return;
    int a = warp / CN;
    int c = warp % CN;
    const float2* row = (const float2*)(x + ((size_t)a * CN + c) * FN);
    float2 v = row[lane];
    float ss = v.x * v.x + v.y * v.y;
    #pragma unroll
    for (int o = 16; o > 0; o >>= 1) ss += __shfl_xor_sync(0xffffffffu, ss, o);
    float inv = 1.0f / fmaxf(sqrtf(ss), 1e-6f);
    float nx = v.x * inv, ny = v.y * inv;

    float2* dst = (float2*)(g_xn + ((size_t)c * AN + a) * FN);
    dst[lane] = make_float2(nx, ny);

    __nv_bfloat162 h2;
    h2.x = __float2bfloat16(nx);
    h2.y = __float2bfloat16(ny);
    ((__nv_bfloat162*)(g_xp + ((size_t)c * AN + a) * 64))[lane] = h2;
}

// ---------------------------------------------------------------------------
// Kernel 2: bf16 screening GEMM, QUARTER sweep per CTA (8 col tiles).
// 1024 jobs balance across 148 SMs (busy SM: 7 jobs = 56 tile-units vs 64).
// Partial top-2 per quarter staged to g_q4 (disjoint col sets -> exact merge).
// ---------------------------------------------------------------------------
#define SM_A    0
#define SM_B0   16384
#define SM_B1   32768
#define SM_RED  49152      // 128 rows x 4 warps x 16B = 8 KB
#define SMEM_BYTES 57344

extern __shared__ __align__(1024) uint8_t dsm[];

__global__ __launch_bounds__(NTHREADS, 2) void k_screen() {
    uint32_t sb = smem_u32(dsm);
    int tid = threadIdx.x;
    int lane = tid & 31;
    int wid = tid >> 5;
    int wm = wid >> 2;
    int wn = wid & 3;
    int c = blockIdx.y;
    int rb = blockIdx.x >> 2;        // row block 0..31
    int qq = blockIdx.x & 3;         // quarter 0..3
    int t0 = qq * 8;
    int row0 = rb * 128;

    const char* xc = (const char*)(g_xp + (size_t)c * AN * 64);  // 128B rows

    uint32_t a_rl = (uint32_t)((lane & 7) + ((lane >> 3) & 1) * 8);
    uint32_t a_cs = (uint32_t)(lane >> 4);
    uint32_t b_nl = (uint32_t)((lane & 7) + (lane >> 4) * 8);
    uint32_t b_cs = (uint32_t)((lane >> 3) & 1);
    uint32_t arow = (uint32_t)(wm * 64);

    float rv1[8], rv2[8];
    int   ri1[8], ri2[8];
    #pragma unroll
    for (int s = 0; s < 8; s++) { rv1[s] = -3.0f; rv2[s] = -4.0f; ri1[s] = 0; ri2[s] = 0; }

    float acc[4][4][4];

    // fold tile pt's accumulators into the running top-2 (branchless).
    auto fold = [&](int pt, bool maskdiag) {
        #pragma unroll
        for (int mi = 0; mi < 4; mi++) {
            #pragma unroll
            for (int hh = 0; hh < 2; hh++) {
                int s = mi * 2 + hh;
                int lrow = wm * 64 + mi * 16 + (lane >> 2) + hh * 8;
                float bv = -5.0f;
                int   bc = 0;
                #pragma unroll
                for (int ni = 0; ni < 4; ni++) {
                    #pragma unroll
                    for (int q = 0; q < 2; q++) {
                        float v = acc[mi][ni][hh * 2 + q];
                        if (maskdiag) {
                            int cc = wn * 32 + ni * 8 + (lane & 3) * 2 + q;
                            v = (cc == lrow) ? -2.0f : v;
                        }
                        int code = ni * 2 + q;       // ascending col within thread
                        bool g = v > bv;             // strict > keeps lowest col
                        bv = g ? v : bv;
                        bc = g ? code : bc;
                    }
                }
                int idx = pt * 128 + wn * 32 + (bc >> 1) * 8 + (lane & 3) * 2 + (bc & 1);
                bool g1 = bv > rv1[s];
                bool g2 = bv > rv2[s];
                ri2[s] = g1 ? ri1[s] : (g2 ? idx : ri2[s]);
                rv2[s] = g1 ? rv1[s] : (g2 ? bv : rv2[s]);
                ri1[s] = g1 ? idx : ri1[s];
                rv1[s] = g1 ? bv : rv1[s];
            }
        }
    };

    // ---- prologue: A tile + B tile t0 (one cp.async group) ----
    #pragma unroll
    for (int u = 0; u < 4; u++) {
        int s = tid + u * NTHREADS;          // 0..1023
        uint32_t r = (uint32_t)(s >> 3), ch = (uint32_t)(s & 7);
        CP16(sb + SM_A  + swz128(r, ch), xc + (size_t)(row0 + r) * 128 + ch * 16);
        CP16(sb + SM_B0 + swz128(r, ch), xc + (size_t)(t0 * 128 + r) * 128 + ch * 16);
    }
    CP_COMMIT();

    for (int tt = 0; tt < 8; tt++) {
        int t = t0 + tt;
        CP_WAIT0();          // tile t's data landed
        __syncthreads();     // publish + fence buffer reuse

        if (tt + 1 < 8) {    // prefetch next B into the other buffer
            uint32_t bufn = sb + ((tt & 1) ? SM_B0 : SM_B1);
            const char* bsrc = xc + (size_t)(t + 1) * 128 * 128;
            #pragma unroll
            for (int u = 0; u < 4; u++) {
                int s = tid + u * NTHREADS;
                uint32_t r = (uint32_t)(s >> 3), ch = (uint32_t)(s & 7);
                CP16(bufn + swz128(r, ch), bsrc + (size_t)r * 128 + ch * 16);
            }
            CP_COMMIT();
        }

        // deferred epilogue of tile t-1 — overlaps the HMMA issue below
        if (tt > 0) {
            if (t - 1 == rb) fold(t - 1, true);
            else             fold(t - 1, false);
        }

        // ---- MMA tile t ----
        #pragma unroll
        for (int mi = 0; mi < 4; mi++)
            #pragma unroll
            for (int ni = 0; ni < 4; ni++)
                #pragma unroll
                for (int q = 0; q < 4; q++) acc[mi][ni][q] = 0.0f;

        uint32_t bufc = sb + ((tt & 1) ? SM_B1 : SM_B0);
        #pragma unroll
        for (int ks = 0; ks < 4; ks++) {
            uint32_t kc = (uint32_t)(ks * 2);
            uint32_t af[4][4], bf[2][4];
            #pragma unroll
            for (int mi = 0; mi < 4; mi++)
                ldsm_x4(af[mi], sb + SM_A + swz128(arow + (uint32_t)(mi * 16) + a_rl, kc + a_cs));
            #pragma unroll
            for (int nh = 0; nh < 2; nh++)
                ldsm_x4(bf[nh], bufc + swz128((uint32_t)(wn * 32 + nh * 16) + b_nl, kc + b_cs));
            #pragma unroll
            for (int mi = 0; mi < 4; mi++)
                #pragma unroll
                for (int ni = 0; ni < 4; ni++)
                    mma_bf16(acc[mi][ni], af[mi], &bf[ni >> 1][(ni & 1) * 2]);
        }
    }

    // fold the last tile of this quarter (exposed — 1/8)
    if (t0 + 7 == rb) fold(t0 + 7, true);
    else              fold(t0 + 7, false);

    // ---- final top-2 reduce: quad -> smem -> 4 wn warps -> g_q4 slot ----
    __syncthreads();
    ulonglong2* red = (ulonglong2*)(dsm + SM_RED);
    #pragma unroll
    for (int mi = 0; mi < 4; mi++) {
        #pragma unroll
        for (int hh = 0; hh < 2; hh++) {
            int s = mi * 2 + hh;
            unsigned long long k1 = pack_key(rv1[s], ri1[s]);
            unsigned long long k2 = pack_key(rv2[s], ri2[s]);
            #pragma unroll
            for (int o = 2; o > 0; o >>= 1) {
                unsigned long long o1 = __shfl_down_sync(0xffffffffu, k1, o, 4);
                unsigned long long o2 = __shfl_down_sync(0xffffffffu, k2, o, 4);
                merge2(k1, k2, o1, o2);
            }
            if ((lane & 3) == 0) {
                int lrow = wm * 64 + mi * 16 + (lane >> 2) + hh * 8;
                red[lrow * 4 + wn] = make_ulonglong2(k1, k2);
            }
        }
    }
    __syncthreads();
    if (tid < 128) {
        ulonglong2 a = red[tid * 4];
        #pragma unroll
        for (int w = 1; w < 4; w++) {
            ulonglong2 b = red[tid * 4 + w];
            merge2(a.x, a.y, b.x, b.y);
        }
        // [c][rb][row][q] — 4 consecutive slots per row for the reader
        g_q4[((size_t)c * AN + row0 + tid) * 4 + qq] = a;
    }
}

// ---------------------------------------------------------------------------
// Kernel 3: merge 4 quarter partials + exact fp32 top-2 refine + loss
// ---------------------------------------------------------------------------
__global__ void k_dist(float* __restrict__ out) {
    int gwarp  = (blockIdx.x * blockDim.x + threadIdx.x) >> 5;
    int lane   = threadIdx.x & 31;
    int nwarps = (gridDim.x * blockDim.x) >> 5;
    float acc = 0.0f;
    for (int item = gwarp; item < CN * AN; item += nwarps) {
        const ulonglong2* st = g_q4 + (size_t)item * 4;   // 64B contiguous
        ulonglong2 k = st[0];
        #pragma unroll
        for (int q = 1; q < 4; q++) {
            ulonglong2 b = st[q];
            merge2(k.x, k.y, b.x, b.y);
        }
        int iA = 4095 - (int)(uint32_t)(k.x & 0xFFFFFFFFull);
        int iB = 4095 - (int)(uint32_t)(k.y & 0xFFFFFFFFull);
        int c = item >> 12;
        const float2* pa = (const float2*)(g_xn + (size_t)item * FN);
        const float2* p1 = (const float2*)(g_xn + ((size_t)c * AN + iA) * FN);
        const float2* p2 = (const float2*)(g_xn + ((size_t)c * AN + iB) * FN);
        float2 va = pa[lane], v1 = p1[lane], v2 = p2[lane];
        float s1 = va.x * v1.x + va.y * v1.y;
        float s2 = va.x * v2.x + va.y * v2.y;
        #pragma unroll
        for (int o = 16; o > 0; o >>= 1) {
            s1 += __shfl_xor_sync(0xffffffffu, s1, o);
            s2 += __shfl_xor_sync(0xffffffffu, s2, o);
        }
        bool useA = (s1 > s2) || (s1 == s2 && iA < iB);
        float2 vb = useA ? v1 : v2;
        float dx = va.x - vb.x + 1e-6f;
        float dy = va.y - vb.y + 1e-6f;
        float ss = dx * dx + dy * dy;
        #pragma unroll
        for (int o = 16; o > 0; o >>= 1) ss += __shfl_xor_sync(0xffffffffu, ss, o);
        if (lane == 0) acc -= logf(sqrtf(ss) + 1e-6f);
    }
    __shared__ float wsum[8];
    __shared__ float smf[256];
    if (lane == 0) wsum[threadIdx.x >> 5] = acc;
    __syncthreads();
    if (threadIdx.x == 0) {
        float s = 0.0f;
        #pragma unroll
        for (int i = 0; i < 8; i++) s += wsum[i];
        g_partial[blockIdx.x] = s;
        __threadfence();
        unsigned t = atomicInc(&g_done, 0xFFFFFFFFu);
        wsum[0] = (t == gridDim.x - 1) ? 1.0f : 0.0f;
    }
    __syncthreads();
    if (wsum[0] != 0.0f) {              // last block: deterministic final sum
        float s = 0.0f;
        #pragma unroll
        for (int u = 0; u < DIST_BLOCKS / 256; u++)
            s += g_partial[threadIdx.x + u * 256];
        smf[threadIdx.x] = s;
        __syncthreads();
        for (int st = 128; st > 0; st >>= 1) {
            if (threadIdx.x < st) smf[threadIdx.x] += smf[threadIdx.x + st];
            __syncthreads();
        }
        if (threadIdx.x == 0) out[0] = smf[0] / (float)(CN * AN);
    }
}

// ---------------------------------------------------------------------------
extern "C" void kernel_launch(void* const* d_in, const int* in_sizes, int n_in,
                              void* d_out, int out_size) {
    const float* x = (const float*)d_in[0];
    float* out = (float*)d_out;
    (void)in_sizes; (void)n_in; (void)out_size;

    cudaFuncSetAttribute(k_screen,
                         cudaFuncAttributeMaxDynamicSharedMemorySize, SMEM_BYTES);

    k_normalize<<<(AN * CN) / 8, NTHREADS>>>(x);
    k_screen<<<dim3(128, CN), NTHREADS, SMEM_BYTES>>>();
    k_dist<<<DIST_BLOCKS, NTHREADS>>>(out);
}

// round 16
// speedup vs baseline: 1.9255x; 1.0376x over previous
#include <cuda_runtime.h>
#include <cuda_bf16.h>
#include <math.h>
#include <stdint.h>

#define AN 4096
#define CN 8
#define FN 64
#define NTHREADS 256
#define DIST_BLOCKS 1024

// ---------------- device scratch (no allocation allowed) --------------------
__device__ float          g_xn[CN * AN * FN];   // [c][a][f] normalized fp32
__device__ __nv_bfloat16  g_xp[CN * AN * 64];   // [c][a][f] bf16 (screen)
__device__ ulonglong2     g_q4[CN * AN * 4];    // row-pass partial top2 [c][a][jq]
__device__ uint32_t       g_cols[CN * 32 * 64 * 128]; // col-pass top1 [c][blk][slot][col]
__device__ float          g_partial[DIST_BLOCKS];
__device__ unsigned int   g_done;

// ---------------- PTX helpers (generic sm_80+ ISA only) ---------------------
static __device__ __forceinline__ uint32_t smem_u32(const void* p) {
    uint32_t a;
    asm("{ .reg .u64 t; cvta.to.shared.u64 t, %1; cvt.u32.u64 %0, t; }"
        : "=r"(a) : "l"(p));
    return a;
}

#define CP16(dst, src) \
    asm volatile("cp.async.cg.shared.global [%0], [%1], 16;" :: "r"(dst), "l"(src))
#define CP_COMMIT() asm volatile("cp.async.commit_group;" ::: "memory")
#define CP_WAIT0()  asm volatile("cp.async.wait_group 0;" ::: "memory")

static __device__ __forceinline__ void ldsm_x4(uint32_t* d, uint32_t addr) {
    asm volatile("ldmatrix.sync.aligned.m8n8.x4.shared.b16 {%0,%1,%2,%3}, [%4];"
                 : "=r"(d[0]), "=r"(d[1]), "=r"(d[2]), "=r"(d[3]) : "r"(addr));
}

static __device__ __forceinline__ void mma_bf16(float* c, const uint32_t* a,
                                                const uint32_t* b) {
    asm volatile(
        "mma.sync.aligned.m16n8k16.row.col.f32.bf16.bf16.f32 "
        "{%0,%1,%2,%3}, {%4,%5,%6,%7}, {%8,%9}, {%0,%1,%2,%3};"
        : "+f"(c[0]), "+f"(c[1]), "+f"(c[2]), "+f"(c[3])
        : "r"(a[0]), "r"(a[1]), "r"(a[2]), "r"(a[3]), "r"(b[0]), "r"(b[1]));
}

// swizzled byte offset of 16B chunk (r, ch) in a 128-row x 128B bf16 tile
static __device__ __forceinline__ uint32_t swz128(uint32_t r, uint32_t ch) {
    return r * 128u + ((ch ^ (r & 7u)) << 4);
}

// order-preserving float -> u32
static __device__ __forceinline__ uint32_t ordf(float v) {
    uint32_t u = __float_as_uint(v);
    return (u & 0x80000000u) ? ~u : (u | 0x80000000u);
}

// packed (ord(val), 4095-idx): u64-max = (max value, then min index)
static __device__ __forceinline__ unsigned long long pack_key(float v, int idx) {
    return ((unsigned long long)ordf(v) << 32) | (uint32_t)(4095 - idx);
}

// top-2 merge of two sorted (k1>=k2) pairs over disjoint candidate sets
static __device__ __forceinline__ void merge2(unsigned long long& a1,
                                              unsigned long long& a2,
                                              unsigned long long b1,
                                              unsigned long long b2) {
    if (b1 > a1) { a2 = (a1 > b2) ? a1 : b2; a1 = b1; }
    else         { a2 = (a2 > b1) ? a2 : b1; }
}

// ---------------------------------------------------------------------------
// Kernel 1: normalize rows -> fp32 (c-major) + bf16 row; reset g_done
// ---------------------------------------------------------------------------
__global__ void k_normalize(const float* __restrict__ x) {
    int gtid = blockIdx.x * blockDim.x + threadIdx.x;
    if (gtid == 0) g_done = 0;
    int warp = gtid >> 5;
    int lane = threadIdx.x & 31;
    if (warp >= AN * CN) return;
    int a = warp / CN;
    int c = warp % CN;
    const float2* row = (const float2*)(x + ((size_t)a * CN + c) * FN);
    float2 v = row[lane];
    float ss = v.x * v.x + v.y * v.y;
    #pragma unroll
    for (int o = 16; o > 0; o >>= 1) ss += __shfl_xor_sync(0xffffffffu, ss, o);
    float inv = 1.0f / fmaxf(sqrtf(ss), 1e-6f);
    float nx = v.x * inv, ny = v.y * inv;

    float2* dst = (float2*)(g_xn + ((size_t)c * AN + a) * FN);
    dst[lane] = make_float2(nx, ny);

    __nv_bfloat162 h2;
    h2.x = __float2bfloat16(nx);
    h2.y = __float2bfloat16(ny);
    ((__nv_bfloat162*)(g_xp + ((size_t)c * AN + a) * 64))[lane] = h2;
}

// ---------------------------------------------------------------------------
// Kernel 2: symmetric-triangle bf16 screening GEMM.
// Job = (row-block ib, strip of <=8 col tiles j>=ib). Row top-2 in regs
// (flushed once per job to g_q4 slot jq); col top-1 per tile-half staged as
// u32 keys to g_cols (unique writer per slot -> no atomics). Deferred fold.
// ---------------------------------------------------------------------------
#define SM_A    0
#define SM_B0   16384
#define SM_B1   32768
#define SM_RED  49152      // 128 rows x 4 warps x 16B = 8 KB
#define SMEM_BYTES 57344

extern __shared__ __align__(1024) uint8_t dsm[];

__global__ __launch_bounds__(NTHREADS, 2) void k_screen() {
    uint32_t sb = smem_u32(dsm);
    int tid = threadIdx.x;
    int lane = tid & 31;
    int wid = tid >> 5;
    int wm = wid >> 2;
    int wn = wid & 3;
    int c = blockIdx.y;

    // decode job (ib, jq) from blockIdx.x in [0, 80)
    int bx = blockIdx.x;
    int ib = 0, jq = 0;
    {
        int cum = 0;
        #pragma unroll 1
        for (int i = 0; i < 32; i++) {
            int n = (32 - i + 7) >> 3;
            if (bx < cum + n) { ib = i; jq = bx - cum; break; }
            cum += n;
        }
    }
    int j0 = ib + jq * 8;
    int nt = min(32, j0 + 8) - j0;   // tiles in this job (1..8)
    int row0 = ib * 128;

    const char* xc = (const char*)(g_xp + (size_t)c * AN * 64);  // 128B rows

    uint32_t a_rl = (uint32_t)((lane & 7) + ((lane >> 3) & 1) * 8);
    uint32_t a_cs = (uint32_t)(lane >> 4);
    uint32_t b_nl = (uint32_t)((lane & 7) + (lane >> 4) * 8);
    uint32_t b_cs = (uint32_t)((lane >> 3) & 1);
    uint32_t arow = (uint32_t)(wm * 64);

    float rv1[8], rv2[8];
    int   ri1[8], ri2[8];
    #pragma unroll
    for (int s = 0; s < 8; s++) { rv1[s] = -3.0f; rv2[s] = -4.0f; ri1[s] = 0; ri2[s] = 0; }

    float acc[4][4][4];

    // fold tile pt (col-block j=pt): row fold into running top-2 + col top-1
    // staging. DIAG==true only for the diagonal tile (mask self, skip cols).
    auto fold = [&](int pt, bool DIAG) {
        uint32_t Lc = (uint32_t)(lane >> 2);      // row-group within warp
        uint32_t ck[8];
        #pragma unroll
        for (int cs = 0; cs < 8; cs++) ck[cs] = 0u;

        #pragma unroll
        for (int mi = 0; mi < 4; mi++) {
            #pragma unroll
            for (int hh = 0; hh < 2; hh++) {
                int s = mi * 2 + hh;
                int lrow = wm * 64 + mi * 16 + (lane >> 2) + hh * 8;
                float bv = -5.0f;
                int   bc = 0;
                uint32_t code = (uint32_t)((hh << 5) | (mi << 3)) | Lc;
                #pragma unroll
                for (int ni = 0; ni < 4; ni++) {
                    #pragma unroll
                    for (int q = 0; q < 2; q++) {
                        float v = acc[mi][ni][hh * 2 + q];
                        if (DIAG) {
                            int cc = wn * 32 + ni * 8 + (lane & 3) * 2 + q;
                            v = (cc == lrow) ? -2.0f : v;
                        }
                        // row: per-tile max (ascending col, strict > = first idx)
                        int cd = ni * 2 + q;
                        bool g = v > bv;
                        bv = g ? v : bv;
                        bc = g ? cd : bc;
                        // col: u32 key max (value | 6-bit row code)
                        if (!DIAG) {
                            uint32_t key = (ordf(v) & 0xFFFFFFC0u) | code;
                            ck[cd] = (key > ck[cd]) ? key : ck[cd];
                        }
                    }
                }
                int idx = pt * 128 + wn * 32 + (bc >> 1) * 8 + (lane & 3) * 2 + (bc & 1);
                bool g1 = bv > rv1[s];
                bool g2 = bv > rv2[s];
                ri2[s] = g1 ? ri1[s] : (g2 ? idx : ri2[s]);
                rv2[s] = g1 ? rv1[s] : (g2 ? bv : rv2[s]);
                ri1[s] = g1 ? idx : ri1[s];
                rv1[s] = g1 ? bv : rv1[s];
            }
        }

        if (!DIAG) {  // reduce col keys over the 8 row-group lanes, stage
            #pragma unroll
            for (int cs = 0; cs < 8; cs++) {
                uint32_t k = ck[cs];
                uint32_t o;
                o = __shfl_down_sync(0xffffffffu, k, 16); k = (o > k) ? o : k;
                o = __shfl_down_sync(0xffffffffu, k, 8);  k = (o > k) ? o : k;
                o = __shfl_down_sync(0xffffffffu, k, 4);  k = (o > k) ? o : k;
                ck[cs] = k;
            }
            if (lane < 4) {
                uint32_t* base = g_cols +
                    (((size_t)c * 32 + pt) * 64 + (2 * ib + wm)) * 128;
                #pragma unroll
                for (int ni = 0; ni < 4; ni++) {
                    uint2 v2 = make_uint2(ck[ni * 2], ck[ni * 2 + 1]);
                    *(uint2*)(base + wn * 32 + ni * 8 + lane * 2) = v2;
                }
            }
        }
    };

    // ---- prologue: A tile + B tile j0 (one cp.async group) ----
    #pragma unroll
    for (int u = 0; u < 4; u++) {
        int s = tid + u * NTHREADS;          // 0..1023
        uint32_t r = (uint32_t)(s >> 3), ch = (uint32_t)(s & 7);
        CP16(sb + SM_A  + swz128(r, ch), xc + (size_t)(row0 + r) * 128 + ch * 16);
        CP16(sb + SM_B0 + swz128(r, ch), xc + (size_t)(j0 * 128 + r) * 128 + ch * 16);
    }
    CP_COMMIT();

    #pragma unroll 1
    for (int tt = 0; tt < nt; tt++) {
        int j = j0 + tt;
        CP_WAIT0();
        __syncthreads();

        if (tt + 1 < nt) {   // prefetch next B into the other buffer
            uint32_t bufn = sb + ((tt & 1) ? SM_B0 : SM_B1);
            const char* bsrc = xc + (size_t)(j + 1) * 128 * 128;
            #pragma unroll
            for (int u = 0; u < 4; u++) {
                int s = tid + u * NTHREADS;
                uint32_t r = (uint32_t)(s >> 3), ch = (uint32_t)(s & 7);
                CP16(bufn + swz128(r, ch), bsrc + (size_t)r * 128 + ch * 16);
            }
            CP_COMMIT();
        }

        // deferred epilogue of tile j-1 — overlaps the HMMA issue below
        if (tt > 0) {
            if (j - 1 == ib) fold(j - 1, true);
            else             fold(j - 1, false);
        }

        // ---- MMA tile j ----
        #pragma unroll
        for (int mi = 0; mi < 4; mi++)
            #pragma unroll
            for (int ni = 0; ni < 4; ni++)
                #pragma unroll
                for (int q = 0; q < 4; q++) acc[mi][ni][q] = 0.0f;

        uint32_t bufc = sb + ((tt & 1) ? SM_B1 : SM_B0);
        #pragma unroll
        for (int ks = 0; ks < 4; ks++) {
            uint32_t kc = (uint32_t)(ks * 2);
            uint32_t af[4][4], bf[2][4];
            #pragma unroll
            for (int mi = 0; mi < 4; mi++)
                ldsm_x4(af[mi], sb + SM_A + swz128(arow + (uint32_t)(mi * 16) + a_rl, kc + a_cs));
            #pragma unroll
            for (int nh = 0; nh < 2; nh++)
                ldsm_x4(bf[nh], bufc + swz128((uint32_t)(wn * 32 + nh * 16) + b_nl, kc + b_cs));
            #pragma unroll
            for (int mi = 0; mi < 4; mi++)
                #pragma unroll
                for (int ni = 0; ni < 4; ni++)
                    mma_bf16(acc[mi][ni], af[mi], &bf[ni >> 1][(ni & 1) * 2]);
        }
    }

    // fold the last tile of this job
    {
        int jl = j0 + nt - 1;
        if (jl == ib) fold(jl, true);
        else          fold(jl, false);
    }

    // ---- row top-2 reduce: quad -> smem -> 4 wn warps -> g_q4 slot jq ----
    __syncthreads();
    ulonglong2* red = (ulonglong2*)(dsm + SM_RED);
    #pragma unroll
    for (int mi = 0; mi < 4; mi++) {
        #pragma unroll
        for (int hh = 0; hh < 2; hh++) {
            int s = mi * 2 + hh;
            unsigned long long k1 = pack_key(rv1[s], ri1[s]);
            unsigned long long k2 = pack_key(rv2[s], ri2[s]);
            #pragma unroll
            for (int o = 2; o > 0; o >>= 1) {
                unsigned long long o1 = __shfl_down_sync(0xffffffffu, k1, o, 4);
                unsigned long long o2 = __shfl_down_sync(0xffffffffu, k2, o, 4);
                merge2(k1, k2, o1, o2);
            }
            if ((lane & 3) == 0) {
                int lrow = wm * 64 + mi * 16 + (lane >> 2) + hh * 8;
                red[lrow * 4 + wn] = make_ulonglong2(k1, k2);
            }
        }
    }
    __syncthreads();
    if (tid < 128) {
        ulonglong2 a = red[tid * 4];
        #pragma unroll
        for (int w = 1; w < 4; w++) {
            ulonglong2 b = red[tid * 4 + w];
            merge2(a.x, a.y, b.x, b.y);
        }
        g_q4[((size_t)c * AN + row0 + tid) * 4 + jq] = a;
    }
}

// ---------------------------------------------------------------------------
// Kernel 3: merge row slots + col slots (lane-parallel + xor-butterfly),
// exact fp32 top-2 refine, distance, fused final reduction.
// ---------------------------------------------------------------------------
__global__ void k_dist(float* __restrict__ out) {
    int gwarp  = (blockIdx.x * blockDim.x + threadIdx.x) >> 5;
    int lane   = threadIdx.x & 31;
    int nwarps = (gridDim.x * blockDim.x) >> 5;
    float acc = 0.0f;
    for (int item = gwarp; item < CN * AN; item += nwarps) {
        int c = item >> 12;
        int a = item & 4095;
        int k = a >> 7;          // row's block
        int r = a & 127;
        int njq = (32 - k + 7) >> 3;

        unsigned long long A1 = 0ull, A2 = 0ull;
        if (lane < njq) {        // disjoint: one row slot per lane
            ulonglong2 kk = g_q4[(size_t)item * 4 + lane];
            A1 = kk.x; A2 = kk.y;
        }
        int ns = 2 * k;          // col slots from tiles (i<k, wm)
        for (int s = lane; s < ns; s += 32) {
            uint32_t key = g_cols[(((size_t)c * 32 + k) * 64 + s) * 128 + r];
            int i = s >> 1, wmm = s & 1;
            int code = key & 63;
            int grow = i * 128 + wmm * 64 + ((code >> 3) & 3) * 16 +
                       (code >> 5) * 8 + (code & 7);
            unsigned long long ck =
                ((unsigned long long)(key & 0xFFFFFFC0u) << 32) |
                (uint32_t)(4095 - grow);
            if (ck > A1) { A2 = A1; A1 = ck; }
            else         { A2 = (A2 > ck) ? A2 : ck; }
        }
        // xor butterfly: partner sets stay disjoint at every level
        #pragma unroll
        for (int o = 16; o > 0; o >>= 1) {
            unsigned long long o1 = __shfl_xor_sync(0xffffffffu, A1, o);
            unsigned long long o2 = __shfl_xor_sync(0xffffffffu, A2, o);
            merge2(A1, A2, o1, o2);
        }

        int iA = 4095 - (int)(uint32_t)(A1 & 0xFFFFFFFFull);
        int iB = 4095 - (int)(uint32_t)(A2 & 0xFFFFFFFFull);
        const float2* pa = (const float2*)(g_xn + (size_t)item * FN);
        const float2* p1 = (const float2*)(g_xn + ((size_t)c * AN + iA) * FN);
        const float2* p2 = (const float2*)(g_xn + ((size_t)c * AN + iB) * FN);
        float2 va = pa[lane], v1 = p1[lane], v2 = p2[lane];
        float s1 = va.x * v1.x + va.y * v1.y;
        float s2 = va.x * v2.x + va.y * v2.y;
        #pragma unroll
        for (int o = 16; o > 0; o >>= 1) {
            s1 += __shfl_xor_sync(0xffffffffu, s1, o);
            s2 += __shfl_xor_sync(0xffffffffu, s2, o);
        }
        bool useA = (s1 > s2) || (s1 == s2 && iA < iB);
        float2 vb = useA ? v1 : v2;
        float dx = va.x - vb.x + 1e-6f;
        float dy = va.y - vb.y + 1e-6f;
        float ss = dx * dx + dy * dy;
        #pragma unroll
        for (int o = 16; o > 0; o >>= 1) ss += __shfl_xor_sync(0xffffffffu, ss, o);
        if (lane == 0) acc -= logf(sqrtf(ss) + 1e-6f);
    }
    __shared__ float wsum[8];
    __shared__ float smf[256];
    if (lane == 0) wsum[threadIdx.x >> 5] = acc;
    __syncthreads();
    if (threadIdx.x == 0) {
        float s = 0.0f;
        #pragma unroll
        for (int i = 0; i < 8; i++) s += wsum[i];
        g_partial[blockIdx.x] = s;
        __threadfence();
        unsigned t = atomicInc(&g_done, 0xFFFFFFFFu);
        wsum[0] = (t == gridDim.x - 1) ? 1.0f : 0.0f;
    }
    __syncthreads();
    if (wsum[0] != 0.0f) {              // last block: deterministic final sum
        float s = 0.0f;
        #pragma unroll
        for (int u = 0; u < DIST_BLOCKS / 256; u++)
            s += g_partial[threadIdx.x + u * 256];
        smf[threadIdx.x] = s;
        __syncthreads();
        for (int st = 128; st > 0; st >>= 1) {
            if (threadIdx.x < st) smf[threadIdx.x] += smf[threadIdx.x + st];
            __syncthreads();
        }
        if (threadIdx.x == 0) out[0] = smf[0] / (float)(CN * AN);
    }
}

// ---------------------------------------------------------------------------
extern "C" void kernel_launch(void* const* d_in, const int* in_sizes, int n_in,
                              void* d_out, int out_size) {
    const float* x = (const float*)d_in[0];
    float* out = (float*)d_out;
    (void)in_sizes; (void)n_in; (void)out_size;

    cudaFuncSetAttribute(k_screen,
                         cudaFuncAttributeMaxDynamicSharedMemorySize, SMEM_BYTES);

    k_normalize<<<(AN * CN) / 8, NTHREADS>>>(x);
    k_screen<<<dim3(80, CN), NTHREADS, SMEM_BYTES>>>();
    k_dist<<<DIST_BLOCKS, NTHREADS>>>(out);
}